// round 6
// baseline (speedup 1.0000x reference)
#include <cuda_runtime.h>
#include <cstdint>

// ---------------------------------------------------------------------------
// VectorQuantizer — emulate fp32 reference pipeline bit-exactly:
//   m_nk = exact fp32 FFMA dot (ascending k, acc from 0)   [R5 change: was TF32 mma]
//   c_n  = warp-butterfly fp32 sum of z_i^2 (offsets 16,8,4,2,1)
//   e2_k = butterfly fp32 sum of e_i^2
//   d2   = fl( fma(m, -2, c) ) + e2   ( == fl(fl(c - 2m) + e2) )
//   argmin = first (lowest) index of min;  q_st = fl(z + fl(q - z))
// Packed f32x2 FMA gives 2 codes per instruction at identical per-lane fp32.
// ---------------------------------------------------------------------------

#define N_ROWS  32768
#define CDIM    32
#define KCODES  8192

#define CTA_MAIN   224
#define GRID_MAIN  147                  // 147*224 = 32928 >= 32768, one wave

#define CODES_PER_CHUNK 128
#define NCHUNKS (KCODES / CODES_PER_CHUNK)   // 64

__device__ __align__(16) float d_eT[CDIM * KCODES];   // eT[i*8192 + k] = emb[k][i]
__device__ __align__(16) float d_e2[KCODES];          // butterfly ||e||^2
__device__ float d_c[N_ROWS];                         // butterfly ||z||^2
__device__ int   d_idx[N_ROWS];
__device__ float d_partials[128];

// ---- packed f32x2 helpers -------------------------------------------------
__device__ __forceinline__ unsigned long long dup2(float x) {
    unsigned long long r;
    asm("mov.b64 %0, {%1, %1};" : "=l"(r) : "f"(x));
    return r;
}
__device__ __forceinline__ unsigned long long ffma2(unsigned long long a,
                                                    unsigned long long b,
                                                    unsigned long long c) {
    unsigned long long d;
    asm("fma.rn.f32x2 %0, %1, %2, %3;" : "=l"(d) : "l"(a), "l"(b), "l"(c));
    return d;
}
__device__ __forceinline__ unsigned long long fadd2(unsigned long long a,
                                                    unsigned long long b) {
    unsigned long long d;
    asm("add.rn.f32x2 %0, %1, %2;" : "=l"(d) : "l"(a), "l"(b));
    return d;
}
__device__ __forceinline__ void unpack2(unsigned long long v, float& lo, float& hi) {
    asm("mov.b64 {%0, %1}, %2;" : "=f"(lo), "=f"(hi) : "l"(v));
}

// XLA GPU warp row-reduce association: shfl.down butterfly 16,8,4,2,1.
__device__ __forceinline__ float butterfly32(float* a) {
#pragma unroll
    for (int off = 16; off >= 1; off >>= 1)
#pragma unroll
        for (int i = 0; i < 16; i++)
            if (i < off) a[i] = __fadd_rn(a[i], a[i + off]);
    return a[0];
}

// ---- P1: transpose emb + e2 -----------------------------------------------
__global__ void vq_prep_codes(const float* __restrict__ emb) {
    int k = blockIdx.x * blockDim.x + threadIdx.x;
    if (k >= KCODES) return;
    float e[CDIM], a[CDIM];
    const float4* er = (const float4*)(emb + (size_t)k * CDIM);
#pragma unroll
    for (int j = 0; j < 8; j++) {
        float4 v = er[j];
        e[4 * j] = v.x; e[4 * j + 1] = v.y; e[4 * j + 2] = v.z; e[4 * j + 3] = v.w;
    }
#pragma unroll
    for (int i = 0; i < CDIM; i++) a[i] = __fmul_rn(e[i], e[i]);
    d_e2[k] = butterfly32(a);
#pragma unroll
    for (int i = 0; i < CDIM; i++) d_eT[i * KCODES + k] = e[i];
}

// ---- P2: c = butterfly ||z||^2 --------------------------------------------
__global__ void vq_prep_rows(const float* __restrict__ z) {
    int n = blockIdx.x * blockDim.x + threadIdx.x;
    if (n >= N_ROWS) return;
    float a[CDIM];
    const float4* zr = (const float4*)(z + (size_t)n * CDIM);
#pragma unroll
    for (int j = 0; j < 8; j++) {
        float4 v = zr[j];
        a[4 * j]     = __fmul_rn(v.x, v.x);
        a[4 * j + 1] = __fmul_rn(v.y, v.y);
        a[4 * j + 2] = __fmul_rn(v.z, v.z);
        a[4 * j + 3] = __fmul_rn(v.w, v.w);
    }
    d_c[n] = butterfly32(a);
}

// ---- main: per-row first-index argmin of bucketed d2 ----------------------
__global__ __launch_bounds__(CTA_MAIN) void vq_argmin_kernel(const float* __restrict__ z) {
    // s_e[i*32 + j]: double2 = element i of codes (cbase+4j .. +3).  16 KB.
    __shared__ double2 s_e[CDIM * 32];
    __shared__ double2 s_b[32];          // e2 of the chunk's 128 codes

    int tid = threadIdx.x;
    int row = blockIdx.x * CTA_MAIN + tid;
    if (row >= N_ROWS) row = N_ROWS - 1;   // duplicate work, deterministic

    unsigned long long zd[CDIM];
    {
        const float4* zr = (const float4*)(z + (size_t)row * CDIM);
#pragma unroll
        for (int j = 0; j < 8; j++) {
            float4 v = zr[j];
            zd[j * 4 + 0] = dup2(v.x);
            zd[j * 4 + 1] = dup2(v.y);
            zd[j * 4 + 2] = dup2(v.z);
            zd[j * 4 + 3] = dup2(v.w);
        }
    }
    unsigned long long cd   = dup2(d_c[row]);
    unsigned long long neg2 = dup2(-2.0f);

    float best = __int_as_float(0x7f800000);   // +inf
    int   bidx = 0;

    const double2* eT2 = (const double2*)d_eT;   // row stride KCODES/4 = 2048
    const double2* e22 = (const double2*)d_e2;

    for (int ch = 0; ch < NCHUNKS; ch++) {
        // stage 32 elements x 32 double2 (=128 codes) + e2
        for (int t = tid; t < CDIM * 32; t += CTA_MAIN) {
            int i = t >> 5, j = t & 31;
            s_e[t] = eT2[i * (KCODES / 4) + ch * 32 + j];
        }
        if (tid < 32) s_b[tid] = e22[ch * 32 + tid];
        __syncthreads();

#pragma unroll 1
        for (int g = 0; g < 32; g += 2) {      // 2 groups x 4 codes in flight
            const double2* p0 = s_e + g;
            const double2* p1 = s_e + g + 1;
            unsigned long long a0 = 0ull, b0 = 0ull, a1 = 0ull, b1 = 0ull;
#pragma unroll
            for (int i = 0; i < CDIM; i++) {   // single ascending FFMA chain
                double2 v0 = p0[i * 32];
                double2 v1 = p1[i * 32];
                a0 = ffma2(zd[i], __double_as_longlong(v0.x), a0);
                b0 = ffma2(zd[i], __double_as_longlong(v0.y), b0);
                a1 = ffma2(zd[i], __double_as_longlong(v1.x), a1);
                b1 = ffma2(zd[i], __double_as_longlong(v1.y), b1);
            }
            double2 ee0 = s_b[g], ee1 = s_b[g + 1];
            // d2 = fl(c - 2m) + e2  (fma single-round == ref's two-step, 2m exact)
            unsigned long long dA = fadd2(ffma2(a0, neg2, cd), __double_as_longlong(ee0.x));
            unsigned long long dB = fadd2(ffma2(b0, neg2, cd), __double_as_longlong(ee0.y));
            unsigned long long dC = fadd2(ffma2(a1, neg2, cd), __double_as_longlong(ee1.x));
            unsigned long long dD = fadd2(ffma2(b1, neg2, cd), __double_as_longlong(ee1.y));
            float s0, s1, s2, s3, s4, s5, s6, s7;
            unpack2(dA, s0, s1); unpack2(dB, s2, s3);
            unpack2(dC, s4, s5); unpack2(dD, s6, s7);
            int k0 = ch * CODES_PER_CHUNK + g * 4;
            // ascending scan + strict '<' == first-index argmin
            if (s0 < best) { best = s0; bidx = k0; }
            if (s1 < best) { best = s1; bidx = k0 + 1; }
            if (s2 < best) { best = s2; bidx = k0 + 2; }
            if (s3 < best) { best = s3; bidx = k0 + 3; }
            if (s4 < best) { best = s4; bidx = k0 + 4; }
            if (s5 < best) { best = s5; bidx = k0 + 5; }
            if (s6 < best) { best = s6; bidx = k0 + 6; }
            if (s7 < best) { best = s7; bidx = k0 + 7; }
        }
        __syncthreads();
    }
    d_idx[row] = bidx;
}

// ---- K3: q_st = fl(z + fl(q - z)), idx, loss partials ---------------------
__global__ void vq_output_kernel(const float* __restrict__ z,
                                 const float* __restrict__ emb,
                                 float* __restrict__ out) {
    __shared__ float warpsum[8];
    int n = blockIdx.x * 256 + threadIdx.x;
    int k = d_idx[n];
    const float* er = emb + (size_t)k * CDIM;
    const float* zr = z + (size_t)n * CDIM;
    float* qr = out + (size_t)n * CDIM;
    float s = 0.f;
#pragma unroll
    for (int j = 0; j < CDIM; j++) {
        float q = er[j], zv = zr[j];
        float dlt = __fadd_rn(q, -zv);
        qr[j] = __fadd_rn(zv, dlt);              // straight-through, exact fp32
        s = __fmaf_rn(dlt, dlt, s);              // loss partial (loose tol)
    }
    out[(size_t)N_ROWS * CDIM + 2 + n] = (float)k;

    int lane = threadIdx.x & 31, wid = threadIdx.x >> 5;
#pragma unroll
    for (int o = 16; o > 0; o >>= 1)
        s += __shfl_down_sync(0xffffffffu, s, o);
    if (lane == 0) warpsum[wid] = s;
    __syncthreads();
    if (wid == 0) {
        float v = (lane < 8) ? warpsum[lane] : 0.f;
#pragma unroll
        for (int o = 4; o > 0; o >>= 1)
            v += __shfl_down_sync(0xffffffffu, v, o);
        if (lane == 0) d_partials[blockIdx.x] = v;
    }
}

// ---- K4: final losses -----------------------------------------------------
__global__ void vq_loss_kernel(float* __restrict__ out) {
    __shared__ float warpsum[4];
    int t = threadIdx.x;
    float s = d_partials[t];
    int lane = t & 31, wid = t >> 5;
#pragma unroll
    for (int o = 16; o > 0; o >>= 1)
        s += __shfl_down_sync(0xffffffffu, s, o);
    if (lane == 0) warpsum[wid] = s;
    __syncthreads();
    if (t == 0) {
        float total = warpsum[0] + warpsum[1] + warpsum[2] + warpsum[3];
        float loss = total / (float)(N_ROWS * CDIM);
        out[(size_t)N_ROWS * CDIM + 0] = loss;   // vq_loss
        out[(size_t)N_ROWS * CDIM + 1] = loss;   // commitment_loss (same value)
    }
}

// ---- entry ----------------------------------------------------------------
extern "C" void kernel_launch(void* const* d_in, const int* in_sizes, int n_in,
                              void* d_out, int out_size) {
    const float* z   = (const float*)d_in[0];
    const float* emb = (const float*)d_in[1];
    if (n_in >= 2 && in_sizes[0] == KCODES * CDIM && in_sizes[1] == N_ROWS * CDIM) {
        const float* t = z; z = emb; emb = t;
    }
    float* out = (float*)d_out;

    vq_prep_codes<<<KCODES / 256, 256>>>(emb);
    vq_prep_rows<<<N_ROWS / 256, 256>>>(z);
    vq_argmin_kernel<<<GRID_MAIN, CTA_MAIN>>>(z);
    vq_output_kernel<<<N_ROWS / 256, 256>>>(z, emb, out);
    vq_loss_kernel<<<1, 128>>>(out);
    (void)out_size;
}

// round 7
// speedup vs baseline: 1.3633x; 1.3633x over previous
#include <cuda_runtime.h>
#include <cstdint>

// ---------------------------------------------------------------------------
// VectorQuantizer — bit-exact fp32 reference emulation (validated R6, rel_err 0):
//   m    = exact fp32 FFMA dot, ascending k, acc from 0
//   c    = warp-butterfly fp32 sum of z^2 (16,8,4,2,1)
//   d2   = fl( fma(m,-2,c) ) + e2,  argmin = first index of min
//   q_st = fl(z + fl(q - z))
// R7: 2 rows/thread (halves LDS per FFMA2), 3-way code split for occupancy,
//     per-split (d2,idx) packed as monotone u64 key, min folded into output.
// ---------------------------------------------------------------------------

#define N_ROWS  32768
#define CDIM    32
#define KCODES  8192

#define CTA_MAIN    128
#define ROWS_PER_T  2
#define ROWBLOCKS   (N_ROWS / (CTA_MAIN * ROWS_PER_T))   // 128
#define NSPLITS     3
#define GRID_MAIN   (ROWBLOCKS * NSPLITS)                // 384

#define CODES_PER_CHUNK 128
#define NCHUNKS (KCODES / CODES_PER_CHUNK)               // 64

__device__ __align__(16) float d_eT[CDIM * KCODES];   // eT[i*8192 + k] = emb[k][i]
__device__ __align__(16) float d_e2[KCODES];          // butterfly ||e||^2
__device__ float d_c[N_ROWS];                         // butterfly ||z||^2
__device__ unsigned long long d_key[NSPLITS * N_ROWS];// (d2bits<<13)|idx per split
__device__ float d_partials[128];

// ---- packed f32x2 helpers -------------------------------------------------
__device__ __forceinline__ unsigned long long dup2(float x) {
    unsigned long long r;
    asm("mov.b64 %0, {%1, %1};" : "=l"(r) : "f"(x));
    return r;
}
__device__ __forceinline__ unsigned long long ffma2(unsigned long long a,
                                                    unsigned long long b,
                                                    unsigned long long c) {
    unsigned long long d;
    asm("fma.rn.f32x2 %0, %1, %2, %3;" : "=l"(d) : "l"(a), "l"(b), "l"(c));
    return d;
}
__device__ __forceinline__ unsigned long long fadd2(unsigned long long a,
                                                    unsigned long long b) {
    unsigned long long d;
    asm("add.rn.f32x2 %0, %1, %2;" : "=l"(d) : "l"(a), "l"(b));
    return d;
}
__device__ __forceinline__ void unpack2(unsigned long long v, float& lo, float& hi) {
    asm("mov.b64 {%0, %1}, %2;" : "=f"(lo), "=f"(hi) : "l"(v));
}

// XLA GPU warp row-reduce association: shfl.down butterfly 16,8,4,2,1.
__device__ __forceinline__ float butterfly32(float* a) {
#pragma unroll
    for (int off = 16; off >= 1; off >>= 1)
#pragma unroll
        for (int i = 0; i < 16; i++)
            if (i < off) a[i] = __fadd_rn(a[i], a[i + off]);
    return a[0];
}

// ---- P1: transpose emb + e2 -----------------------------------------------
__global__ void vq_prep_codes(const float* __restrict__ emb) {
    int k = blockIdx.x * blockDim.x + threadIdx.x;
    if (k >= KCODES) return;
    float e[CDIM], a[CDIM];
    const float4* er = (const float4*)(emb + (size_t)k * CDIM);
#pragma unroll
    for (int j = 0; j < 8; j++) {
        float4 v = er[j];
        e[4 * j] = v.x; e[4 * j + 1] = v.y; e[4 * j + 2] = v.z; e[4 * j + 3] = v.w;
    }
#pragma unroll
    for (int i = 0; i < CDIM; i++) a[i] = __fmul_rn(e[i], e[i]);
    d_e2[k] = butterfly32(a);
#pragma unroll
    for (int i = 0; i < CDIM; i++) d_eT[i * KCODES + k] = e[i];
}

// ---- P2: c = butterfly ||z||^2 --------------------------------------------
__global__ void vq_prep_rows(const float* __restrict__ z) {
    int n = blockIdx.x * blockDim.x + threadIdx.x;
    if (n >= N_ROWS) return;
    float a[CDIM];
    const float4* zr = (const float4*)(z + (size_t)n * CDIM);
#pragma unroll
    for (int j = 0; j < 8; j++) {
        float4 v = zr[j];
        a[4 * j]     = __fmul_rn(v.x, v.x);
        a[4 * j + 1] = __fmul_rn(v.y, v.y);
        a[4 * j + 2] = __fmul_rn(v.z, v.z);
        a[4 * j + 3] = __fmul_rn(v.w, v.w);
    }
    d_c[n] = butterfly32(a);
}

// ---- main: 2 rows/thread, per-split argmin --------------------------------
__global__ __launch_bounds__(CTA_MAIN, 3) void vq_argmin_kernel(const float* __restrict__ z) {
    __shared__ double2 s_e[CDIM * 32];   // 32 double2 cols = 128 codes/chunk, 16KB
    __shared__ double2 s_b[32];          // e2 of the chunk's 128 codes

    int tid = threadIdx.x;
    int sp  = blockIdx.x / ROWBLOCKS;    // code split 0..2
    int rb  = blockIdx.x % ROWBLOCKS;
    int rowA = rb * (CTA_MAIN * ROWS_PER_T) + tid;
    int rowB = rowA + CTA_MAIN;

    int ch_lo = (sp * NCHUNKS) / NSPLITS;          // 0,21,42
    int ch_hi = ((sp + 1) * NCHUNKS) / NSPLITS;    // 21,42,64

    unsigned long long zdA[CDIM], zdB[CDIM];
    {
        const float4* ra = (const float4*)(z + (size_t)rowA * CDIM);
        const float4* rbp = (const float4*)(z + (size_t)rowB * CDIM);
#pragma unroll
        for (int j = 0; j < 8; j++) {
            float4 va = ra[j], vb = rbp[j];
            zdA[4 * j] = dup2(va.x); zdA[4 * j + 1] = dup2(va.y);
            zdA[4 * j + 2] = dup2(va.z); zdA[4 * j + 3] = dup2(va.w);
            zdB[4 * j] = dup2(vb.x); zdB[4 * j + 1] = dup2(vb.y);
            zdB[4 * j + 2] = dup2(vb.z); zdB[4 * j + 3] = dup2(vb.w);
        }
    }
    unsigned long long cdA = dup2(d_c[rowA]);
    unsigned long long cdB = dup2(d_c[rowB]);
    unsigned long long neg2 = dup2(-2.0f);

    float bestA = __int_as_float(0x7f800000), bestB = bestA;
    int   idxA = 0, idxB = 0;

    const double2* eT2 = (const double2*)d_eT;   // row stride KCODES/4 = 2048
    const double2* e22 = (const double2*)d_e2;

    for (int ch = ch_lo; ch < ch_hi; ch++) {
        // stage 32 elements x 32 double2 (=128 codes) + e2
        for (int t = tid; t < CDIM * 32; t += CTA_MAIN) {
            int i = t >> 5, j = t & 31;
            s_e[t] = eT2[i * (KCODES / 4) + ch * 32 + j];
        }
        if (tid < 32) s_b[tid] = e22[ch * 32 + tid];
        __syncthreads();

#pragma unroll 1
        for (int g = 0; g < 32; g++) {           // 4 codes x 2 rows in flight
            const double2* pe = s_e + g;
            unsigned long long aA0 = 0ull, aA1 = 0ull, aB0 = 0ull, aB1 = 0ull;
#pragma unroll
            for (int i = 0; i < CDIM; i++) {     // single ascending FFMA chain
                double2 v = pe[i * 32];          // broadcast LDS.128: 4 codes' elem i
                unsigned long long vx = __double_as_longlong(v.x);
                unsigned long long vy = __double_as_longlong(v.y);
                aA0 = ffma2(zdA[i], vx, aA0);
                aA1 = ffma2(zdA[i], vy, aA1);
                aB0 = ffma2(zdB[i], vx, aB0);
                aB1 = ffma2(zdB[i], vy, aB1);
            }
            double2 ee = s_b[g];
            unsigned long long e2x = __double_as_longlong(ee.x);
            unsigned long long e2y = __double_as_longlong(ee.y);
            // d2 = fl(c - 2m) + e2  (fma single-round == ref two-step, 2m exact)
            unsigned long long dA0 = fadd2(ffma2(aA0, neg2, cdA), e2x);
            unsigned long long dA1 = fadd2(ffma2(aA1, neg2, cdA), e2y);
            unsigned long long dB0 = fadd2(ffma2(aB0, neg2, cdB), e2x);
            unsigned long long dB1 = fadd2(ffma2(aB1, neg2, cdB), e2y);
            float a0, a1, a2, a3, b0, b1, b2, b3;
            unpack2(dA0, a0, a1); unpack2(dA1, a2, a3);
            unpack2(dB0, b0, b1); unpack2(dB1, b2, b3);
            int k0 = ch * CODES_PER_CHUNK + g * 4;
            // ascending scan + strict '<' == first-index argmin
            if (a0 < bestA) { bestA = a0; idxA = k0; }
            if (a1 < bestA) { bestA = a1; idxA = k0 + 1; }
            if (a2 < bestA) { bestA = a2; idxA = k0 + 2; }
            if (a3 < bestA) { bestA = a3; idxA = k0 + 3; }
            if (b0 < bestB) { bestB = b0; idxB = k0; }
            if (b1 < bestB) { bestB = b1; idxB = k0 + 1; }
            if (b2 < bestB) { bestB = b2; idxB = k0 + 2; }
            if (b3 < bestB) { bestB = b3; idxB = k0 + 3; }
        }
        __syncthreads();
    }
    // monotone key: d2 > 0 so float bits order == value order; low 13 bits = idx
    d_key[sp * N_ROWS + rowA] =
        ((unsigned long long)__float_as_uint(bestA) << 13) | (unsigned)idxA;
    d_key[sp * N_ROWS + rowB] =
        ((unsigned long long)__float_as_uint(bestB) << 13) | (unsigned)idxB;
}

// ---- K3: fold split keys, q_st = fl(z + fl(q - z)), idx, loss partials ----
__global__ void vq_output_kernel(const float* __restrict__ z,
                                 const float* __restrict__ emb,
                                 float* __restrict__ out) {
    __shared__ float warpsum[8];
    int n = blockIdx.x * 256 + threadIdx.x;
    unsigned long long k0 = d_key[n];
    unsigned long long k1 = d_key[N_ROWS + n];
    unsigned long long k2 = d_key[2 * N_ROWS + n];
    unsigned long long km = k0 < k1 ? k0 : k1;
    km = km < k2 ? km : k2;
    int k = (int)(km & 0x1FFFu);

    const float* er = emb + (size_t)k * CDIM;
    const float* zr = z + (size_t)n * CDIM;
    float* qr = out + (size_t)n * CDIM;
    float s = 0.f;
#pragma unroll
    for (int j = 0; j < CDIM; j++) {
        float q = er[j], zv = zr[j];
        float dlt = __fadd_rn(q, -zv);
        qr[j] = __fadd_rn(zv, dlt);              // straight-through, exact fp32
        s = __fmaf_rn(dlt, dlt, s);              // loss partial (loose tol)
    }
    out[(size_t)N_ROWS * CDIM + 2 + n] = (float)k;

    int lane = threadIdx.x & 31, wid = threadIdx.x >> 5;
#pragma unroll
    for (int o = 16; o > 0; o >>= 1)
        s += __shfl_down_sync(0xffffffffu, s, o);
    if (lane == 0) warpsum[wid] = s;
    __syncthreads();
    if (wid == 0) {
        float v = (lane < 8) ? warpsum[lane] : 0.f;
#pragma unroll
        for (int o = 4; o > 0; o >>= 1)
            v += __shfl_down_sync(0xffffffffu, v, o);
        if (lane == 0) d_partials[blockIdx.x] = v;
    }
}

// ---- K4: final losses -----------------------------------------------------
__global__ void vq_loss_kernel(float* __restrict__ out) {
    __shared__ float warpsum[4];
    int t = threadIdx.x;
    float s = d_partials[t];
    int lane = t & 31, wid = t >> 5;
#pragma unroll
    for (int o = 16; o > 0; o >>= 1)
        s += __shfl_down_sync(0xffffffffu, s, o);
    if (lane == 0) warpsum[wid] = s;
    __syncthreads();
    if (t == 0) {
        float total = warpsum[0] + warpsum[1] + warpsum[2] + warpsum[3];
        float loss = total / (float)(N_ROWS * CDIM);
        out[(size_t)N_ROWS * CDIM + 0] = loss;   // vq_loss
        out[(size_t)N_ROWS * CDIM + 1] = loss;   // commitment_loss (same value)
    }
}

// ---- entry ----------------------------------------------------------------
extern "C" void kernel_launch(void* const* d_in, const int* in_sizes, int n_in,
                              void* d_out, int out_size) {
    const float* z   = (const float*)d_in[0];
    const float* emb = (const float*)d_in[1];
    if (n_in >= 2 && in_sizes[0] == KCODES * CDIM && in_sizes[1] == N_ROWS * CDIM) {
        const float* t = z; z = emb; emb = t;
    }
    float* out = (float*)d_out;

    vq_prep_codes<<<KCODES / 256, 256>>>(emb);
    vq_prep_rows<<<N_ROWS / 256, 256>>>(z);
    vq_argmin_kernel<<<GRID_MAIN, CTA_MAIN>>>(z);
    vq_output_kernel<<<N_ROWS / 256, 256>>>(z, emb, out);
    vq_loss_kernel<<<1, 128>>>(out);
    (void)out_size;
}